// round 15
// baseline (speedup 1.0000x reference)
#include <cuda_runtime.h>
#include <cuda_bf16.h>
#include <cstdint>
#include <cstddef>
#include <math.h>

#define BATCH   8
#define SEQ     2048
#define DIM     512
#define HEADS   8
#define DH      64
#define HID     512
#define TOK     (BATCH*SEQ)          /* 16384 */
#define QKVN    (3*HID)              /* 1536 */
#define NROWS   (TOK*HEADS)          /* 131072 q/k rows of 64 */

// Scratch — referenced ONLY from device code (host-side symbol decay gives the
// host shadow address, which GB300 ATS dereferences silently to zeros).
__device__ __align__(256) float g_q[(size_t)TOK*HID];   // [b][h][n][d] fp32
__device__ __align__(256) float g_k[(size_t)TOK*HID];
__device__ __align__(256) float g_v[(size_t)TOK*HID];
__device__ __align__(256) uint32_t g_xh32[(size_t)TOK*(DIM/2)];
__device__ __align__(256) uint32_t g_xl32[(size_t)TOK*(DIM/2)];
__device__ __align__(256) uint32_t g_oh32[(size_t)TOK*(HID/2)];
__device__ __align__(256) uint32_t g_ol32[(size_t)TOK*(HID/2)];
__device__ __align__(256) uint32_t g_wqh[(size_t)QKVN*(DIM/2)];
__device__ __align__(256) uint32_t g_wql[(size_t)QKVN*(DIM/2)];
__device__ __align__(256) uint32_t g_woh[(size_t)DIM*(HID/2)];
__device__ __align__(256) uint32_t g_wol[(size_t)DIM*(HID/2)];
__device__ __align__(256) uint32_t g_qh32[(size_t)NROWS*32];
__device__ __align__(256) uint32_t g_ql32[(size_t)NROWS*32];
__device__ __align__(256) uint32_t g_kh32[(size_t)NROWS*32];
__device__ __align__(256) uint32_t g_kl32[(size_t)NROWS*32];
__device__ __align__(256) uint32_t g_vth32[(size_t)BATCH*HEADS*DH*(SEQ/2)];
__device__ __align__(256) uint32_t g_vtl32[(size_t)BATCH*HEADS*DH*(SEQ/2)];

// ---------------------------------------------------------------------------
// helpers
// ---------------------------------------------------------------------------
__device__ __forceinline__ uint32_t pack_bf16(float lo, float hi) {
    uint32_t r;
    asm("cvt.rn.bf16x2.f32 %0, %1, %2;" : "=r"(r) : "f"(hi), "f"(lo));
    return r;
}
__device__ __forceinline__ uint32_t residual_pack(uint32_t h, float e0, float e1) {
    float f0 = __uint_as_float(h << 16);
    float f1 = __uint_as_float(h & 0xFFFF0000u);
    return pack_bf16(e0 - f0, e1 - f1);
}
__device__ __forceinline__ void mma16816(float* c, const uint32_t* a,
                                         uint32_t b0, uint32_t b1) {
    asm volatile("mma.sync.aligned.m16n8k16.row.col.f32.bf16.bf16.f32 "
        "{%0,%1,%2,%3}, {%4,%5,%6,%7}, {%8,%9}, {%0,%1,%2,%3};"
        : "+f"(c[0]), "+f"(c[1]), "+f"(c[2]), "+f"(c[3])
        : "r"(a[0]), "r"(a[1]), "r"(a[2]), "r"(a[3]), "r"(b0), "r"(b1));
}
__device__ __forceinline__ void ldsm4(uint32_t* r, uint32_t a) {
    asm volatile("ldmatrix.sync.aligned.m8n8.x4.shared.b16 {%0,%1,%2,%3}, [%4];"
        : "=r"(r[0]), "=r"(r[1]), "=r"(r[2]), "=r"(r[3]) : "r"(a));
}
__device__ __forceinline__ uint32_t smem_u32(const void* p) {
    uint32_t a;
    asm("{ .reg .u64 t; cvta.to.shared.u64 t, %1; cvt.u32.u64 %0, t; }"
        : "=r"(a) : "l"(p));
    return a;
}
__device__ __forceinline__ float ex2f(float x) {
    float y; asm("ex2.approx.f32 %0, %1;" : "=f"(y) : "f"(x)); return y;
}
__device__ __forceinline__ void cpa16(uint32_t dst, const void* src) {
    asm volatile("cp.async.ca.shared.global [%0], [%1], 16;"
                 :: "r"(dst), "l"(src) : "memory");
}
__device__ __forceinline__ void cpa_commit() {
    asm volatile("cp.async.commit_group;" ::: "memory");
}
template <int NG>
__device__ __forceinline__ void cpa_wait() {
    asm volatile("cp.async.wait_group %0;" :: "n"(NG) : "memory");
}

// ---------------------------------------------------------------------------
// 1) RMSNorm -> packed bf16 hi/lo
// ---------------------------------------------------------------------------
__global__ void rmsnorm_kernel(const float* __restrict__ x,
                               const float* __restrict__ g) {
    int row = blockIdx.x;
    const float4* xr = (const float4*)(x + (size_t)row * DIM);
    int tid = threadIdx.x;
    float4 xv = xr[tid];
    float ss = xv.x*xv.x + xv.y*xv.y + xv.z*xv.z + xv.w*xv.w;
    #pragma unroll
    for (int m = 16; m; m >>= 1) ss += __shfl_xor_sync(0xffffffffu, ss, m);
    __shared__ float sred[4];
    int warp = tid >> 5, lane = tid & 31;
    if (lane == 0) sred[warp] = ss;
    __syncthreads();
    ss = sred[0] + sred[1] + sred[2] + sred[3];
    float inv = 22.627416997969522f / fmaxf(sqrtf(ss), 1e-12f);
    float4 gv = ((const float4*)g)[tid];
    float o0 = xv.x * inv * gv.x, o1 = xv.y * inv * gv.y;
    float o2 = xv.z * inv * gv.z, o3 = xv.w * inv * gv.w;
    uint32_t h01 = pack_bf16(o0, o1), h23 = pack_bf16(o2, o3);
    size_t base = (size_t)row * (DIM/2) + 2 * tid;
    g_xh32[base] = h01;
    g_xh32[base + 1] = h23;
    g_xl32[base] = residual_pack(h01, o0, o1);
    g_xl32[base + 1] = residual_pack(h23, o2, o3);
}

// ---------------------------------------------------------------------------
// 2) weight transpose + split
// ---------------------------------------------------------------------------
template <int WHICH>   // 0: w_qkv -> g_wq*   1: w_out -> g_wo*
__global__ void wt_prep_kernel(const float* __restrict__ w) {
    const int N = WHICH ? DIM : QKVN;
    const int Kh = (WHICH ? HID : DIM) / 2;
    int i = blockIdx.x * 256 + threadIdx.x;
    int n = i / Kh, kp = i - n * Kh;
    float v0 = w[(size_t)(2 * kp) * N + n];
    float v1 = w[(size_t)(2 * kp + 1) * N + n];
    uint32_t h = pack_bf16(v0, v1);
    uint32_t* dh = WHICH ? g_woh : g_wqh;
    uint32_t* dl = WHICH ? g_wol : g_wql;
    dh[i] = h;
    dl[i] = residual_pack(h, v0, v1);
}

// ---------------------------------------------------------------------------
// 3) bf16 3-term compensated GEMM — attention-style: A fragments from global
//    (registers), B staged via cp.async double buffer. CTA 256m x 64n,
//    512 threads (16 warps x 16-row strips). Dyn smem: 2 x 18432 B.
// ---------------------------------------------------------------------------
#define GEMM_STAGE 18432
#define GEMM_SMEM  (2 * GEMM_STAGE)

template <int WHICH>
__global__ void __launch_bounds__(512, 1)
gemm_bf16_kernel(float* __restrict__ C) {
    const int N  = WHICH ? DIM : QKVN;
    const int Kp = (WHICH ? HID : DIM) / 2;   // u32 per row
    const uint32_t* Ah = WHICH ? g_oh32 : g_xh32;
    const uint32_t* Al = WHICH ? g_ol32 : g_xl32;
    const uint32_t* Bh = WHICH ? g_woh : g_wqh;
    const uint32_t* Bl = WHICH ? g_wol : g_wql;

    extern __shared__ __align__(16) uint32_t smg[];
    uint32_t sb = smem_u32(smg);

    int tid = threadIdx.x, w = tid >> 5, l = tid & 31;
    int g = l >> 2, c = l & 3;
    int m0 = blockIdx.y << 8, n0 = blockIdx.x << 6;

    float acc[8][4];
    #pragma unroll
    for (int t = 0; t < 8; t++)
        #pragma unroll
        for (int i = 0; i < 4; i++) acc[t][i] = 0.0f;

    int lrow = (l & 7) + ((l >> 4) & 1) * 8;
    int lcol = ((l >> 3) & 1) * 8;
    uint32_t off_l = (uint32_t)(lrow * 72 + lcol) * 2;

    size_t r0 = (size_t)(m0 + 16 * w + g) * Kp;
    size_t r1 = r0 + (size_t)8 * Kp;

    int srow = tid >> 3, sq4 = tid & 7;          // B staging: 1 uint4/plane
    uint32_t se = srow * 144 + sq4 * 16;

    auto issue = [&](int kb, int s) {
        uint32_t sbase = sb + (uint32_t)s * GEMM_STAGE;
        cpa16(sbase + se,        Bh + (size_t)(n0 + srow) * Kp + kb * 32 + sq4 * 4);
        cpa16(sbase + se + 9216, Bl + (size_t)(n0 + srow) * Kp + kb * 32 + sq4 * 4);
    };

    int nKb = Kp >> 5;                     // 64-bf16 (32-u32) k blocks
    issue(0, 0); cpa_commit();
    for (int kb = 0; kb < nKb; kb++) {
        // A fragments for this k-block (Q-fragment pattern, from global)
        uint32_t aqh[4][4], aql[4][4];
        #pragma unroll
        for (int kk = 0; kk < 4; kk++) {
            int cu = kb * 32 + (kk << 3) + c;
            aqh[kk][0] = Ah[r0 + cu];
            aqh[kk][1] = Ah[r1 + cu];
            aqh[kk][2] = Ah[r0 + cu + 4];
            aqh[kk][3] = Ah[r1 + cu + 4];
            aql[kk][0] = Al[r0 + cu];
            aql[kk][1] = Al[r1 + cu];
            aql[kk][2] = Al[r0 + cu + 4];
            aql[kk][3] = Al[r1 + cu + 4];
        }
        int s = kb & 1;
        if (kb + 1 < nKb) { issue(kb + 1, s ^ 1); cpa_commit(); cpa_wait<1>(); }
        else              { cpa_wait<0>(); }
        __syncthreads();

        uint32_t aBh = sb + (uint32_t)s * GEMM_STAGE + off_l;
        uint32_t aBl = aBh + 9216;

        #pragma unroll
        for (int kk = 0; kk < 4; kk++) {
            #pragma unroll
            for (int tp = 0; tp < 4; tp++) {
                uint32_t bh4[4], bl4[4];
                uint32_t off = (uint32_t)(tp * 16 * 72 + kk * 16) * 2;
                ldsm4(bh4, aBh + off);
                ldsm4(bl4, aBl + off);
                mma16816(acc[2*tp],   aqh[kk], bh4[0], bh4[1]);
                mma16816(acc[2*tp],   aql[kk], bh4[0], bh4[1]);
                mma16816(acc[2*tp],   aqh[kk], bl4[0], bl4[1]);
                mma16816(acc[2*tp+1], aqh[kk], bh4[2], bh4[3]);
                mma16816(acc[2*tp+1], aql[kk], bh4[2], bh4[3]);
                mma16816(acc[2*tp+1], aqh[kk], bl4[2], bl4[3]);
            }
        }
        __syncthreads();
    }

    // epilogue
    int row0 = m0 + 16 * w + g;
    #pragma unroll
    for (int t = 0; t < 8; t++) {
        int col = n0 + 8 * t + 2 * c;
        if (WHICH == 1) {
            *(float2*)(C + (size_t)row0 * N + col) = make_float2(acc[t][0], acc[t][1]);
            *(float2*)(C + (size_t)(row0 + 8) * N + col) = make_float2(acc[t][2], acc[t][3]);
        } else {
            int which = col >> 9;
            int hh = (col >> 6) & 7;
            int d = col & 63;
            float* dst = (which == 0) ? g_q : (which == 1) ? g_k : g_v;
            int bb = row0 >> 11, nn = row0 & 2047;
            size_t o0 = (((size_t)((bb << 3) + hh) * SEQ + nn) << 6) + d;
            size_t o1 = (((size_t)((bb << 3) + hh) * SEQ + (nn + 8)) << 6) + d;
            *(float2*)(dst + o0) = make_float2(acc[t][0], acc[t][1]);
            *(float2*)(dst + o1) = make_float2(acc[t][2], acc[t][3]);
        }
    }
}

// ---------------------------------------------------------------------------
// 4) q/k prep
// ---------------------------------------------------------------------------
__global__ void qk_prep_kernel(const float* __restrict__ scale, float mult, int which) {
    const float* src = which ? g_k : g_q;
    uint32_t* dh = which ? g_kh32 : g_qh32;
    uint32_t* dl = which ? g_kl32 : g_ql32;
    int gw = blockIdx.x * 8 + (threadIdx.x >> 5);
    int lane = threadIdx.x & 31;
    float2 v = ((const float2*)(src + (size_t)gw * DH))[lane];
    float ss = v.x * v.x + v.y * v.y;
    #pragma unroll
    for (int m = 16; m; m >>= 1) ss += __shfl_xor_sync(0xffffffffu, ss, m);
    float inv = mult / fmaxf(sqrtf(ss), 1e-12f);
    v.x *= inv * scale[lane * 2];
    v.y *= inv * scale[lane * 2 + 1];
    uint32_t h = pack_bf16(v.x, v.y);
    dh[(size_t)gw * 32 + lane] = h;
    dl[(size_t)gw * 32 + lane] = residual_pack(h, v.x, v.y);
}

// ---------------------------------------------------------------------------
// 5) V prep
// ---------------------------------------------------------------------------
__global__ void v_prep_kernel() {
    __shared__ float tile[64][68];
    int bh = blockIdx.y, n0 = blockIdx.x << 6, tid = threadIdx.x;
    const float* V = g_v + ((size_t)bh * SEQ + n0) * DH;
    #pragma unroll
    for (int i = 0; i < 4; i++) {
        int idx = tid + (i << 8);
        int r = idx >> 4, c4 = idx & 15;
        *(float4*)&tile[r][c4 * 4] = ((const float4*)V)[idx];
    }
    __syncthreads();
    #pragma unroll
    for (int i = 0; i < 8; i++) {
        int idx = tid + (i << 8);
        int d = idx >> 5, kp = idx & 31;
        float v0 = tile[2 * kp][d], v1 = tile[2 * kp + 1][d];
        uint32_t h = pack_bf16(v0, v1);
        size_t oi = ((size_t)bh * DH + d) * (SEQ / 2) + (n0 >> 1) + kp;
        g_vth32[oi] = h;
        g_vtl32[oi] = residual_pack(h, v0, v1);
    }
}

// ---------------------------------------------------------------------------
// 6) Flash attention, double-buffered K/V, 512 threads (16 warps x 16 q-rows,
//    256-query tile). Dynamic smem: 2 x 36864 B.  (unchanged from R13)
// ---------------------------------------------------------------------------
#define ATTN_STAGE 36864
#define ATTN_SMEM  (2 * ATTN_STAGE)

__global__ void __launch_bounds__(512, 1) attn_mma_kernel() {
    extern __shared__ __align__(16) uint32_t sma[];
    uint32_t sb = smem_u32(sma);

    int tid = threadIdx.x, w = tid >> 5, l = tid & 31;
    int g = l >> 2, c = l & 3;
    int bh = blockIdx.y, q0 = blockIdx.x << 8;   // 256-query tile

    uint32_t aqh[4][4], aql[4][4];
    {
        size_t r0 = (size_t)(bh * SEQ + q0 + 16 * w + g) * 32;
        size_t r1 = r0 + 8 * 32;
        #pragma unroll
        for (int kk = 0; kk < 4; kk++) {
            int cu = (kk << 3) + c;
            aqh[kk][0] = g_qh32[r0 + cu];
            aqh[kk][1] = g_qh32[r1 + cu];
            aqh[kk][2] = g_qh32[r0 + cu + 4];
            aqh[kk][3] = g_qh32[r1 + cu + 4];
            aql[kk][0] = g_ql32[r0 + cu];
            aql[kk][1] = g_ql32[r1 + cu];
            aql[kk][2] = g_ql32[r0 + cu + 4];
            aql[kk][3] = g_ql32[r1 + cu + 4];
        }
    }

    float o[8][4];
    #pragma unroll
    for (int t = 0; t < 8; t++)
        #pragma unroll
        for (int i = 0; i < 4; i++) o[t][i] = 0.0f;
    float lsum0 = 0.0f, lsum1 = 0.0f;

    int lrow = (l & 7) + ((l >> 4) & 1) * 8;
    int lcol = ((l >> 3) & 1) * 8;
    uint32_t off_l = (uint32_t)(lrow * 72 + lcol) * 2;

    const uint32_t* Kh = g_kh32 + (size_t)(bh * SEQ) * 32;
    const uint32_t* Kl = g_kl32 + (size_t)(bh * SEQ) * 32;
    const uint32_t* Vh = g_vth32 + (size_t)bh * DH * (SEQ / 2);
    const uint32_t* Vl = g_vtl32 + (size_t)bh * DH * (SEQ / 2);

    int srow = tid >> 3, sq4a = tid & 7;          // 1 uint4/plane/thread
    uint32_t se0 = srow * 144 + sq4a * 16;

    auto issue = [&](int j0, int s) {
        uint32_t sbase = sb + (uint32_t)s * ATTN_STAGE;
        const uint32_t* kh = Kh + (size_t)(j0 + srow) * 32 + sq4a * 4;
        const uint32_t* kl = Kl + (size_t)(j0 + srow) * 32 + sq4a * 4;
        const uint32_t* vh = Vh + (size_t)srow * (SEQ / 2) + (j0 >> 1) + sq4a * 4;
        const uint32_t* vl = Vl + (size_t)srow * (SEQ / 2) + (j0 >> 1) + sq4a * 4;
        cpa16(sbase + se0,          kh);
        cpa16(sbase + se0 + 9216,   kl);
        cpa16(sbase + se0 + 18432,  vh);
        cpa16(sbase + se0 + 27648,  vl);
    };

    issue(0, 0); cpa_commit();
    for (int j0 = 0; j0 < SEQ; j0 += 64) {
        int s = (j0 >> 6) & 1;
        if (j0 + 64 < SEQ) { issue(j0 + 64, s ^ 1); cpa_commit(); cpa_wait<1>(); }
        else               { cpa_wait<0>(); }
        __syncthreads();

        uint32_t aKh = sb + (uint32_t)s * ATTN_STAGE + off_l;
        uint32_t aKl = aKh + 9216;
        uint32_t aVh = aKh + 18432;
        uint32_t aVl = aKh + 27648;

        float sreg[8][4];
        #pragma unroll
        for (int t = 0; t < 8; t++)
            #pragma unroll
            for (int i = 0; i < 4; i++) sreg[t][i] = 0.0f;

        #pragma unroll
        for (int kk = 0; kk < 4; kk++) {
            #pragma unroll
            for (int tp = 0; tp < 4; tp++) {
                uint32_t bh4[4], bl4[4];
                uint32_t off = (uint32_t)(tp * 16 * 72 + kk * 16) * 2;
                ldsm4(bh4, aKh + off);
                ldsm4(bl4, aKl + off);
                mma16816(sreg[2*tp],   aqh[kk], bh4[0], bh4[1]);
                mma16816(sreg[2*tp],   aql[kk], bh4[0], bh4[1]);
                mma16816(sreg[2*tp],   aqh[kk], bl4[0], bl4[1]);
                mma16816(sreg[2*tp+1], aqh[kk], bh4[2], bh4[3]);
                mma16816(sreg[2*tp+1], aql[kk], bh4[2], bh4[3]);
                mma16816(sreg[2*tp+1], aqh[kk], bl4[2], bl4[3]);
            }
        }

        uint32_t ph[4][4], pl[4][4];
        #pragma unroll
        for (int t = 0; t < 8; t++) {
            float e0 = ex2f(fmaf(sreg[t][0], 1.4426950408889634f, -11.541560327111707f));
            float e1 = ex2f(fmaf(sreg[t][1], 1.4426950408889634f, -11.541560327111707f));
            float e2 = ex2f(fmaf(sreg[t][2], 1.4426950408889634f, -11.541560327111707f));
            float e3 = ex2f(fmaf(sreg[t][3], 1.4426950408889634f, -11.541560327111707f));
            lsum0 += e0 + e1;
            lsum1 += e2 + e3;
            uint32_t h01 = pack_bf16(e0, e1), h23 = pack_bf16(e2, e3);
            uint32_t l01 = residual_pack(h01, e0, e1);
            uint32_t l23 = residual_pack(h23, e2, e3);
            int kk = t >> 1, half = (t & 1) << 1;
            ph[kk][half] = h01; ph[kk][half + 1] = h23;
            pl[kk][half] = l01; pl[kk][half + 1] = l23;
        }

        #pragma unroll
        for (int kk = 0; kk < 4; kk++) {
            #pragma unroll
            for (int tp = 0; tp < 4; tp++) {
                uint32_t vh4[4], vl4[4];
                uint32_t off = (uint32_t)(tp * 16 * 72 + kk * 16) * 2;
                ldsm4(vh4, aVh + off);
                ldsm4(vl4, aVl + off);
                mma16816(o[2*tp],   ph[kk], vh4[0], vh4[1]);
                mma16816(o[2*tp],   pl[kk], vh4[0], vh4[1]);
                mma16816(o[2*tp],   ph[kk], vl4[0], vl4[1]);
                mma16816(o[2*tp+1], ph[kk], vh4[2], vh4[3]);
                mma16816(o[2*tp+1], pl[kk], vh4[2], vh4[3]);
                mma16816(o[2*tp+1], ph[kk], vl4[2], vl4[3]);
            }
        }
        __syncthreads();
    }

    lsum0 += __shfl_xor_sync(0xffffffffu, lsum0, 1);
    lsum0 += __shfl_xor_sync(0xffffffffu, lsum0, 2);
    lsum1 += __shfl_xor_sync(0xffffffffu, lsum1, 1);
    lsum1 += __shfl_xor_sync(0xffffffffu, lsum1, 2);
    float inv0 = 1.0f / lsum0, inv1 = 1.0f / lsum1;

    int b = bh >> 3, h = bh & 7;
    int nr = q0 + 16 * w + g;
    size_t base0 = (size_t)(b * SEQ + nr) * (HID / 2) + h * 32;
    size_t base1 = (size_t)(b * SEQ + nr + 8) * (HID / 2) + h * 32;
    #pragma unroll
    for (int t = 0; t < 8; t++) {
        int pc = 4 * t + c;
        float e0 = o[t][0] * inv0, e1 = o[t][1] * inv0;
        float e2 = o[t][2] * inv1, e3 = o[t][3] * inv1;
        uint32_t h0 = pack_bf16(e0, e1);
        uint32_t h1 = pack_bf16(e2, e3);
        g_oh32[base0 + pc] = h0;
        g_ol32[base0 + pc] = residual_pack(h0, e0, e1);
        g_oh32[base1 + pc] = h1;
        g_ol32[base1 + pc] = residual_pack(h1, e2, e3);
    }
}

// ---------------------------------------------------------------------------
extern "C" void kernel_launch(void* const* d_in, const int* in_sizes, int n_in,
                              void* d_out, int out_size) {
    const float* x       = (const float*)d_in[0];
    const float* g       = (const float*)d_in[1];
    const float* w_qkv   = (const float*)d_in[2];
    const float* q_scale = (const float*)d_in[3];
    const float* k_scale = (const float*)d_in[4];
    const float* w_out   = (const float*)d_in[5];
    float* out = (float*)d_out;
    (void)in_sizes; (void)n_in; (void)out_size;

    cudaFuncSetAttribute(gemm_bf16_kernel<0>,
                         cudaFuncAttributeMaxDynamicSharedMemorySize, GEMM_SMEM);
    cudaFuncSetAttribute(gemm_bf16_kernel<1>,
                         cudaFuncAttributeMaxDynamicSharedMemorySize, GEMM_SMEM);
    cudaFuncSetAttribute(attn_mma_kernel,
                         cudaFuncAttributeMaxDynamicSharedMemorySize, ATTN_SMEM);

    rmsnorm_kernel<<<TOK, 128>>>(x, g);
    wt_prep_kernel<0><<<QKVN * (DIM / 2) / 256, 256>>>(w_qkv);
    wt_prep_kernel<1><<<DIM * (HID / 2) / 256, 256>>>(w_out);
    gemm_bf16_kernel<0><<<dim3(QKVN / 64, TOK / 256), 512, GEMM_SMEM>>>(nullptr);
    qk_prep_kernel<<<NROWS / 8, 256>>>(q_scale, 8.0f, 0);
    qk_prep_kernel<<<NROWS / 8, 256>>>(k_scale, 1.0f, 1);
    v_prep_kernel<<<dim3(SEQ / 64, BATCH * HEADS), 256>>>();
    attn_mma_kernel<<<dim3(SEQ / 256, BATCH * HEADS), 512, ATTN_SMEM>>>();
    gemm_bf16_kernel<1><<<dim3(DIM / 64, TOK / 256), 512, GEMM_SMEM>>>(out);
}

// round 16
// speedup vs baseline: 1.2726x; 1.2726x over previous
#include <cuda_runtime.h>
#include <cuda_bf16.h>
#include <cstdint>
#include <cstddef>
#include <math.h>

#define BATCH   8
#define SEQ     2048
#define DIM     512
#define HEADS   8
#define DH      64
#define HID     512
#define TOK     (BATCH*SEQ)          /* 16384 */
#define QKVN    (3*HID)              /* 1536 */
#define NROWS   (TOK*HEADS)          /* 131072 q/k rows of 64 */

// Scratch — referenced ONLY from device code (host-side symbol decay gives the
// host shadow address, which GB300 ATS dereferences silently to zeros).
__device__ __align__(256) float g_q[(size_t)TOK*HID];   // [b][h][n][d] fp32
__device__ __align__(256) float g_k[(size_t)TOK*HID];
__device__ __align__(256) float g_v[(size_t)TOK*HID];
__device__ __align__(256) uint32_t g_xh32[(size_t)TOK*(DIM/2)];
__device__ __align__(256) uint32_t g_xl32[(size_t)TOK*(DIM/2)];
__device__ __align__(256) uint32_t g_oh32[(size_t)TOK*(HID/2)];
__device__ __align__(256) uint32_t g_ol32[(size_t)TOK*(HID/2)];
__device__ __align__(256) uint32_t g_wqh[(size_t)QKVN*(DIM/2)];
__device__ __align__(256) uint32_t g_wql[(size_t)QKVN*(DIM/2)];
__device__ __align__(256) uint32_t g_woh[(size_t)DIM*(HID/2)];
__device__ __align__(256) uint32_t g_wol[(size_t)DIM*(HID/2)];
__device__ __align__(256) uint32_t g_qh32[(size_t)NROWS*32];
__device__ __align__(256) uint32_t g_ql32[(size_t)NROWS*32];
__device__ __align__(256) uint32_t g_kh32[(size_t)NROWS*32];
__device__ __align__(256) uint32_t g_kl32[(size_t)NROWS*32];
__device__ __align__(256) uint32_t g_vth32[(size_t)BATCH*HEADS*DH*(SEQ/2)];
__device__ __align__(256) uint32_t g_vtl32[(size_t)BATCH*HEADS*DH*(SEQ/2)];

// ---------------------------------------------------------------------------
// helpers
// ---------------------------------------------------------------------------
__device__ __forceinline__ uint32_t pack_bf16(float lo, float hi) {
    uint32_t r;
    asm("cvt.rn.bf16x2.f32 %0, %1, %2;" : "=r"(r) : "f"(hi), "f"(lo));
    return r;
}
__device__ __forceinline__ uint32_t residual_pack(uint32_t h, float e0, float e1) {
    float f0 = __uint_as_float(h << 16);
    float f1 = __uint_as_float(h & 0xFFFF0000u);
    return pack_bf16(e0 - f0, e1 - f1);
}
__device__ __forceinline__ void mma16816(float* c, const uint32_t* a,
                                         uint32_t b0, uint32_t b1) {
    asm volatile("mma.sync.aligned.m16n8k16.row.col.f32.bf16.bf16.f32 "
        "{%0,%1,%2,%3}, {%4,%5,%6,%7}, {%8,%9}, {%0,%1,%2,%3};"
        : "+f"(c[0]), "+f"(c[1]), "+f"(c[2]), "+f"(c[3])
        : "r"(a[0]), "r"(a[1]), "r"(a[2]), "r"(a[3]), "r"(b0), "r"(b1));
}
__device__ __forceinline__ void ldsm4(uint32_t* r, uint32_t a) {
    asm volatile("ldmatrix.sync.aligned.m8n8.x4.shared.b16 {%0,%1,%2,%3}, [%4];"
        : "=r"(r[0]), "=r"(r[1]), "=r"(r[2]), "=r"(r[3]) : "r"(a));
}
__device__ __forceinline__ uint32_t smem_u32(const void* p) {
    uint32_t a;
    asm("{ .reg .u64 t; cvta.to.shared.u64 t, %1; cvt.u32.u64 %0, t; }"
        : "=r"(a) : "l"(p));
    return a;
}
__device__ __forceinline__ float ex2f(float x) {
    float y; asm("ex2.approx.f32 %0, %1;" : "=f"(y) : "f"(x)); return y;
}
__device__ __forceinline__ void cpa16(uint32_t dst, const void* src) {
    asm volatile("cp.async.ca.shared.global [%0], [%1], 16;"
                 :: "r"(dst), "l"(src) : "memory");
}
__device__ __forceinline__ void cpa_commit() {
    asm volatile("cp.async.commit_group;" ::: "memory");
}
template <int NG>
__device__ __forceinline__ void cpa_wait() {
    asm volatile("cp.async.wait_group %0;" :: "n"(NG) : "memory");
}

// ---------------------------------------------------------------------------
// 1) RMSNorm -> packed bf16 hi/lo
// ---------------------------------------------------------------------------
__global__ void rmsnorm_kernel(const float* __restrict__ x,
                               const float* __restrict__ g) {
    int row = blockIdx.x;
    const float4* xr = (const float4*)(x + (size_t)row * DIM);
    int tid = threadIdx.x;
    float4 xv = xr[tid];
    float ss = xv.x*xv.x + xv.y*xv.y + xv.z*xv.z + xv.w*xv.w;
    #pragma unroll
    for (int m = 16; m; m >>= 1) ss += __shfl_xor_sync(0xffffffffu, ss, m);
    __shared__ float sred[4];
    int warp = tid >> 5, lane = tid & 31;
    if (lane == 0) sred[warp] = ss;
    __syncthreads();
    ss = sred[0] + sred[1] + sred[2] + sred[3];
    float inv = 22.627416997969522f / fmaxf(sqrtf(ss), 1e-12f);
    float4 gv = ((const float4*)g)[tid];
    float o0 = xv.x * inv * gv.x, o1 = xv.y * inv * gv.y;
    float o2 = xv.z * inv * gv.z, o3 = xv.w * inv * gv.w;
    uint32_t h01 = pack_bf16(o0, o1), h23 = pack_bf16(o2, o3);
    size_t base = (size_t)row * (DIM/2) + 2 * tid;
    g_xh32[base] = h01;
    g_xh32[base + 1] = h23;
    g_xl32[base] = residual_pack(h01, o0, o1);
    g_xl32[base + 1] = residual_pack(h23, o2, o3);
}

// ---------------------------------------------------------------------------
// 2) weight transpose + split
// ---------------------------------------------------------------------------
template <int WHICH>   // 0: w_qkv -> g_wq*   1: w_out -> g_wo*
__global__ void wt_prep_kernel(const float* __restrict__ w) {
    const int N = WHICH ? DIM : QKVN;
    const int Kh = (WHICH ? HID : DIM) / 2;
    int i = blockIdx.x * 256 + threadIdx.x;
    int n = i / Kh, kp = i - n * Kh;
    float v0 = w[(size_t)(2 * kp) * N + n];
    float v1 = w[(size_t)(2 * kp + 1) * N + n];
    uint32_t h = pack_bf16(v0, v1);
    uint32_t* dh = WHICH ? g_woh : g_wqh;
    uint32_t* dl = WHICH ? g_wol : g_wql;
    dh[i] = h;
    dl[i] = residual_pack(h, v0, v1);
}

// ---------------------------------------------------------------------------
// 3) bf16 3-term compensated GEMM, 3-stage cp.async ring (1 sync/iter),
//    512 threads (16 warps, 32x32 tiles). Dyn smem: 3 x 40960 B.
// ---------------------------------------------------------------------------
#define GEMM_STAGE 40960
#define GEMM_SMEM  (3 * GEMM_STAGE)

template <int WHICH>
__global__ void __launch_bounds__(512, 1)
gemm_bf16_kernel(float* __restrict__ C) {
    const int N  = WHICH ? DIM : QKVN;
    const int Kp = (WHICH ? HID : DIM) / 2;   // u32 per row
    const uint32_t* Ah = WHICH ? g_oh32 : g_xh32;
    const uint32_t* Al = WHICH ? g_ol32 : g_xl32;
    const uint32_t* Bh = WHICH ? g_woh : g_wqh;
    const uint32_t* Bl = WHICH ? g_wol : g_wql;

    extern __shared__ __align__(16) uint32_t smg[];
    uint32_t sb = smem_u32(smg);

    int tid = threadIdx.x, w = tid >> 5, l = tid & 31;
    int g = l >> 2, c = l & 3;
    int mw = w >> 2, nw = w & 3;      // 4x4 warp grid, 32x32 tiles
    int m0 = blockIdx.y << 7, n0 = blockIdx.x << 7;

    float acc[2][4][4];
    #pragma unroll
    for (int i = 0; i < 2; i++)
        #pragma unroll
        for (int j = 0; j < 4; j++)
            #pragma unroll
            for (int e = 0; e < 4; e++) acc[i][j][e] = 0.0f;

    uint32_t offA = (uint32_t)((mw * 32 + (l & 15)) * 80 + ((l >> 4) << 4));
    int lrB = (l & 7) + ((l >> 4) & 1) * 8;
    int lcB = ((l >> 3) & 1) << 3;
    uint32_t offB = (uint32_t)((nw * 32 + lrB) * 80 + lcB * 2);

    int srow0 = tid >> 2, sq4 = tid & 3;        // staging: 1 uint4/plane/thread
    uint32_t sd0 = srow0 * 80 + sq4 * 16;

    auto issue = [&](int kb, int s) {
        uint32_t sbase = sb + (uint32_t)s * GEMM_STAGE;
        const uint32_t* ga = Ah + (size_t)(m0 + srow0) * Kp + kb * 16 + sq4 * 4;
        const uint32_t* gl = Al + (size_t)(m0 + srow0) * Kp + kb * 16 + sq4 * 4;
        const uint32_t* gb = Bh + (size_t)(n0 + srow0) * Kp + kb * 16 + sq4 * 4;
        const uint32_t* gc = Bl + (size_t)(n0 + srow0) * Kp + kb * 16 + sq4 * 4;
        cpa16(sbase + sd0,          ga);
        cpa16(sbase + sd0 + 10240,  gl);
        cpa16(sbase + sd0 + 20480,  gb);
        cpa16(sbase + sd0 + 30720,  gc);
    };

    int nK = Kp >> 4;                     // 32-bf16 (16-u32) k blocks (16 or 8)
    issue(0, 0); cpa_commit();
    issue(1, 1); cpa_commit();
    for (int kb = 0; kb < nK; kb++) {
        int s = kb % 3;
        if (kb == nK - 1) cpa_wait<0>(); else cpa_wait<1>();
        __syncthreads();
        if (kb + 2 < nK) { issue(kb + 2, (kb + 2) % 3); cpa_commit(); }

        uint32_t aAh = sb + (uint32_t)s * GEMM_STAGE + offA;
        uint32_t aAl = aAh + 10240;
        uint32_t aBh = sb + (uint32_t)s * GEMM_STAGE + 20480 + offB;
        uint32_t aBl = aBh + 10240;

        #pragma unroll
        for (int kk = 0; kk < 2; kk++) {
            uint32_t ah[2][4], al[2][4];
            #pragma unroll
            for (int mt = 0; mt < 2; mt++) {
                ldsm4(ah[mt], aAh + mt * 1280 + kk * 32);
                ldsm4(al[mt], aAl + mt * 1280 + kk * 32);
            }
            #pragma unroll
            for (int np = 0; np < 2; np++) {
                uint32_t bh4[4], bl4[4];
                ldsm4(bh4, aBh + np * 1280 + kk * 32);
                ldsm4(bl4, aBl + np * 1280 + kk * 32);
                #pragma unroll
                for (int mt = 0; mt < 2; mt++) {
                    float* c0 = acc[mt][2 * np];
                    float* c1 = acc[mt][2 * np + 1];
                    mma16816(c0, ah[mt], bh4[0], bh4[1]);
                    mma16816(c0, al[mt], bh4[0], bh4[1]);
                    mma16816(c0, ah[mt], bl4[0], bl4[1]);
                    mma16816(c1, ah[mt], bh4[2], bh4[3]);
                    mma16816(c1, al[mt], bh4[2], bh4[3]);
                    mma16816(c1, ah[mt], bl4[2], bl4[3]);
                }
            }
        }
    }

    // epilogue
    #pragma unroll
    for (int mt = 0; mt < 2; mt++) {
        int row = m0 + mw * 32 + mt * 16 + g;
        #pragma unroll
        for (int nt = 0; nt < 4; nt++) {
            int col = n0 + nw * 32 + nt * 8 + 2 * c;
            if (WHICH == 1) {
                *(float2*)(C + (size_t)row * N + col) =
                    make_float2(acc[mt][nt][0], acc[mt][nt][1]);
                *(float2*)(C + (size_t)(row + 8) * N + col) =
                    make_float2(acc[mt][nt][2], acc[mt][nt][3]);
            } else {
                int which = col >> 9;
                int hh = (col >> 6) & 7;
                int d = col & 63;
                float* dst = (which == 0) ? g_q : (which == 1) ? g_k : g_v;
                int bb = row >> 11, nn = row & 2047;
                size_t o0 = (((size_t)((bb << 3) + hh) * SEQ + nn) << 6) + d;
                size_t o1 = (((size_t)((bb << 3) + hh) * SEQ + (nn + 8)) << 6) + d;
                *(float2*)(dst + o0) = make_float2(acc[mt][nt][0], acc[mt][nt][1]);
                *(float2*)(dst + o1) = make_float2(acc[mt][nt][2], acc[mt][nt][3]);
            }
        }
    }
}

// ---------------------------------------------------------------------------
// 4) q/k prep
// ---------------------------------------------------------------------------
__global__ void qk_prep_kernel(const float* __restrict__ scale, float mult, int which) {
    const float* src = which ? g_k : g_q;
    uint32_t* dh = which ? g_kh32 : g_qh32;
    uint32_t* dl = which ? g_kl32 : g_ql32;
    int gw = blockIdx.x * 8 + (threadIdx.x >> 5);
    int lane = threadIdx.x & 31;
    float2 v = ((const float2*)(src + (size_t)gw * DH))[lane];
    float ss = v.x * v.x + v.y * v.y;
    #pragma unroll
    for (int m = 16; m; m >>= 1) ss += __shfl_xor_sync(0xffffffffu, ss, m);
    float inv = mult / fmaxf(sqrtf(ss), 1e-12f);
    v.x *= inv * scale[lane * 2];
    v.y *= inv * scale[lane * 2 + 1];
    uint32_t h = pack_bf16(v.x, v.y);
    dh[(size_t)gw * 32 + lane] = h;
    dl[(size_t)gw * 32 + lane] = residual_pack(h, v.x, v.y);
}

// ---------------------------------------------------------------------------
// 5) V prep
// ---------------------------------------------------------------------------
__global__ void v_prep_kernel() {
    __shared__ float tile[64][68];
    int bh = blockIdx.y, n0 = blockIdx.x << 6, tid = threadIdx.x;
    const float* V = g_v + ((size_t)bh * SEQ + n0) * DH;
    #pragma unroll
    for (int i = 0; i < 4; i++) {
        int idx = tid + (i << 8);
        int r = idx >> 4, c4 = idx & 15;
        *(float4*)&tile[r][c4 * 4] = ((const float4*)V)[idx];
    }
    __syncthreads();
    #pragma unroll
    for (int i = 0; i < 8; i++) {
        int idx = tid + (i << 8);
        int d = idx >> 5, kp = idx & 31;
        float v0 = tile[2 * kp][d], v1 = tile[2 * kp + 1][d];
        uint32_t h = pack_bf16(v0, v1);
        size_t oi = ((size_t)bh * DH + d) * (SEQ / 2) + (n0 >> 1) + kp;
        g_vth32[oi] = h;
        g_vtl32[oi] = residual_pack(h, v0, v1);
    }
}

// ---------------------------------------------------------------------------
// 6) Flash attention, 3-stage cp.async ring (1 sync/iter), 512 threads
//    (16 warps x 16 q-rows, 256-query tile). Dyn smem: 3 x 36864 B.
// ---------------------------------------------------------------------------
#define ATTN_STAGE 36864
#define ATTN_SMEM  (3 * ATTN_STAGE)

__global__ void __launch_bounds__(512, 1) attn_mma_kernel() {
    extern __shared__ __align__(16) uint32_t sma[];
    uint32_t sb = smem_u32(sma);

    int tid = threadIdx.x, w = tid >> 5, l = tid & 31;
    int g = l >> 2, c = l & 3;
    int bh = blockIdx.y, q0 = blockIdx.x << 8;   // 256-query tile

    uint32_t aqh[4][4], aql[4][4];
    {
        size_t r0 = (size_t)(bh * SEQ + q0 + 16 * w + g) * 32;
        size_t r1 = r0 + 8 * 32;
        #pragma unroll
        for (int kk = 0; kk < 4; kk++) {
            int cu = (kk << 3) + c;
            aqh[kk][0] = g_qh32[r0 + cu];
            aqh[kk][1] = g_qh32[r1 + cu];
            aqh[kk][2] = g_qh32[r0 + cu + 4];
            aqh[kk][3] = g_qh32[r1 + cu + 4];
            aql[kk][0] = g_ql32[r0 + cu];
            aql[kk][1] = g_ql32[r1 + cu];
            aql[kk][2] = g_ql32[r0 + cu + 4];
            aql[kk][3] = g_ql32[r1 + cu + 4];
        }
    }

    float o[8][4];
    #pragma unroll
    for (int t = 0; t < 8; t++)
        #pragma unroll
        for (int i = 0; i < 4; i++) o[t][i] = 0.0f;
    float lsum0 = 0.0f, lsum1 = 0.0f;

    int lrow = (l & 7) + ((l >> 4) & 1) * 8;
    int lcol = ((l >> 3) & 1) * 8;
    uint32_t off_l = (uint32_t)(lrow * 72 + lcol) * 2;

    const uint32_t* Kh = g_kh32 + (size_t)(bh * SEQ) * 32;
    const uint32_t* Kl = g_kl32 + (size_t)(bh * SEQ) * 32;
    const uint32_t* Vh = g_vth32 + (size_t)bh * DH * (SEQ / 2);
    const uint32_t* Vl = g_vtl32 + (size_t)bh * DH * (SEQ / 2);

    int srow = tid >> 3, sq4a = tid & 7;          // 1 uint4/plane/thread
    uint32_t se0 = srow * 144 + sq4a * 16;

    auto issue = [&](int j0, int s) {
        uint32_t sbase = sb + (uint32_t)s * ATTN_STAGE;
        const uint32_t* kh = Kh + (size_t)(j0 + srow) * 32 + sq4a * 4;
        const uint32_t* kl = Kl + (size_t)(j0 + srow) * 32 + sq4a * 4;
        const uint32_t* vh = Vh + (size_t)srow * (SEQ / 2) + (j0 >> 1) + sq4a * 4;
        const uint32_t* vl = Vl + (size_t)srow * (SEQ / 2) + (j0 >> 1) + sq4a * 4;
        cpa16(sbase + se0,          kh);
        cpa16(sbase + se0 + 9216,   kl);
        cpa16(sbase + se0 + 18432,  vh);
        cpa16(sbase + se0 + 27648,  vl);
    };

    issue(0, 0); cpa_commit();
    issue(64, 1); cpa_commit();
    for (int j0 = 0; j0 < SEQ; j0 += 64) {
        int jb = j0 >> 6;
        int s = jb % 3;
        if (j0 + 64 >= SEQ) cpa_wait<0>(); else cpa_wait<1>();
        __syncthreads();
        if (j0 + 128 < SEQ) { issue(j0 + 128, (jb + 2) % 3); cpa_commit(); }

        uint32_t aKh = sb + (uint32_t)s * ATTN_STAGE + off_l;
        uint32_t aKl = aKh + 9216;
        uint32_t aVh = aKh + 18432;
        uint32_t aVl = aKh + 27648;

        float sreg[8][4];
        #pragma unroll
        for (int t = 0; t < 8; t++)
            #pragma unroll
            for (int i = 0; i < 4; i++) sreg[t][i] = 0.0f;

        #pragma unroll
        for (int kk = 0; kk < 4; kk++) {
            #pragma unroll
            for (int tp = 0; tp < 4; tp++) {
                uint32_t bh4[4], bl4[4];
                uint32_t off = (uint32_t)(tp * 16 * 72 + kk * 16) * 2;
                ldsm4(bh4, aKh + off);
                ldsm4(bl4, aKl + off);
                mma16816(sreg[2*tp],   aqh[kk], bh4[0], bh4[1]);
                mma16816(sreg[2*tp],   aql[kk], bh4[0], bh4[1]);
                mma16816(sreg[2*tp],   aqh[kk], bl4[0], bl4[1]);
                mma16816(sreg[2*tp+1], aqh[kk], bh4[2], bh4[3]);
                mma16816(sreg[2*tp+1], aql[kk], bh4[2], bh4[3]);
                mma16816(sreg[2*tp+1], aqh[kk], bl4[2], bl4[3]);
            }
        }

        uint32_t ph[4][4], pl[4][4];
        #pragma unroll
        for (int t = 0; t < 8; t++) {
            float e0 = ex2f(fmaf(sreg[t][0], 1.4426950408889634f, -11.541560327111707f));
            float e1 = ex2f(fmaf(sreg[t][1], 1.4426950408889634f, -11.541560327111707f));
            float e2 = ex2f(fmaf(sreg[t][2], 1.4426950408889634f, -11.541560327111707f));
            float e3 = ex2f(fmaf(sreg[t][3], 1.4426950408889634f, -11.541560327111707f));
            lsum0 += e0 + e1;
            lsum1 += e2 + e3;
            uint32_t h01 = pack_bf16(e0, e1), h23 = pack_bf16(e2, e3);
            uint32_t l01 = residual_pack(h01, e0, e1);
            uint32_t l23 = residual_pack(h23, e2, e3);
            int kk = t >> 1, half = (t & 1) << 1;
            ph[kk][half] = h01; ph[kk][half + 1] = h23;
            pl[kk][half] = l01; pl[kk][half + 1] = l23;
        }

        #pragma unroll
        for (int kk = 0; kk < 4; kk++) {
            #pragma unroll
            for (int tp = 0; tp < 4; tp++) {
                uint32_t vh4[4], vl4[4];
                uint32_t off = (uint32_t)(tp * 16 * 72 + kk * 16) * 2;
                ldsm4(vh4, aVh + off);
                ldsm4(vl4, aVl + off);
                mma16816(o[2*tp],   ph[kk], vh4[0], vh4[1]);
                mma16816(o[2*tp],   pl[kk], vh4[0], vh4[1]);
                mma16816(o[2*tp],   ph[kk], vl4[0], vl4[1]);
                mma16816(o[2*tp+1], ph[kk], vh4[2], vh4[3]);
                mma16816(o[2*tp+1], pl[kk], vh4[2], vh4[3]);
                mma16816(o[2*tp+1], ph[kk], vl4[2], vl4[3]);
            }
        }
    }

    lsum0 += __shfl_xor_sync(0xffffffffu, lsum0, 1);
    lsum0 += __shfl_xor_sync(0xffffffffu, lsum0, 2);
    lsum1 += __shfl_xor_sync(0xffffffffu, lsum1, 1);
    lsum1 += __shfl_xor_sync(0xffffffffu, lsum1, 2);
    float inv0 = 1.0f / lsum0, inv1 = 1.0f / lsum1;

    int b = bh >> 3, h = bh & 7;
    int nr = q0 + 16 * w + g;
    size_t base0 = (size_t)(b * SEQ + nr) * (HID / 2) + h * 32;
    size_t base1 = (size_t)(b * SEQ + nr + 8) * (HID / 2) + h * 32;
    #pragma unroll
    for (int t = 0; t < 8; t++) {
        int pc = 4 * t + c;
        float e0 = o[t][0] * inv0, e1 = o[t][1] * inv0;
        float e2 = o[t][2] * inv1, e3 = o[t][3] * inv1;
        uint32_t h0 = pack_bf16(e0, e1);
        uint32_t h1 = pack_bf16(e2, e3);
        g_oh32[base0 + pc] = h0;
        g_ol32[base0 + pc] = residual_pack(h0, e0, e1);
        g_oh32[base1 + pc] = h1;
        g_ol32[base1 + pc] = residual_pack(h1, e2, e3);
    }
}

// ---------------------------------------------------------------------------
extern "C" void kernel_launch(void* const* d_in, const int* in_sizes, int n_in,
                              void* d_out, int out_size) {
    const float* x       = (const float*)d_in[0];
    const float* g       = (const float*)d_in[1];
    const float* w_qkv   = (const float*)d_in[2];
    const float* q_scale = (const float*)d_in[3];
    const float* k_scale = (const float*)d_in[4];
    const float* w_out   = (const float*)d_in[5];
    float* out = (float*)d_out;
    (void)in_sizes; (void)n_in; (void)out_size;

    cudaFuncSetAttribute(gemm_bf16_kernel<0>,
                         cudaFuncAttributeMaxDynamicSharedMemorySize, GEMM_SMEM);
    cudaFuncSetAttribute(gemm_bf16_kernel<1>,
                         cudaFuncAttributeMaxDynamicSharedMemorySize, GEMM_SMEM);
    cudaFuncSetAttribute(attn_mma_kernel,
                         cudaFuncAttributeMaxDynamicSharedMemorySize, ATTN_SMEM);

    rmsnorm_kernel<<<TOK, 128>>>(x, g);
    wt_prep_kernel<0><<<QKVN * (DIM / 2) / 256, 256>>>(w_qkv);
    wt_prep_kernel<1><<<DIM * (HID / 2) / 256, 256>>>(w_out);
    gemm_bf16_kernel<0><<<dim3(QKVN / 128, TOK / 128), 512, GEMM_SMEM>>>(nullptr);
    qk_prep_kernel<<<NROWS / 8, 256>>>(q_scale, 8.0f, 0);
    qk_prep_kernel<<<NROWS / 8, 256>>>(k_scale, 1.0f, 1);
    v_prep_kernel<<<dim3(SEQ / 64, BATCH * HEADS), 256>>>();
    attn_mma_kernel<<<dim3(SEQ / 256, BATCH * HEADS), 512, ATTN_SMEM>>>();
    gemm_bf16_kernel<1><<<dim3(DIM / 128, TOK / 128), 512, GEMM_SMEM>>>(out);
}